// round 5
// baseline (speedup 1.0000x reference)
#include <cuda_runtime.h>
#include <cuda_bf16.h>
#include <math.h>

// Problem constants
#define NN   1024
#define DD   128
#define DIN  137
#define NL   3
#define IPB  7      // i-rows per agg block (147 blocks = 1 wave on 148 SMs)
#define YD   16     // j-partitions per agg block (1024-thread blocks)
#define ACR  4      // rows per block (and k-slices) in fused GEMM kernels

typedef unsigned long long ull;

// ---------------- scratch (device globals; no allocation allowed) -----------
__device__ float g_h  [NN * DD];
__device__ float g_a  [NN * DD];   // pre-scaled by 1/sqrt(2)
__device__ float g_cb [NN * DD];   // (c + bm) pre-scaled by 1/sqrt(2)
__device__ float g_agg[NN * DD];

// ---------------- packed f32x2 helpers --------------------------------------
__device__ __forceinline__ ull pk2(float a, float b) {
    ull r; asm("mov.b64 %0, {%1,%2};" : "=l"(r) : "f"(a), "f"(b)); return r;
}
__device__ __forceinline__ ull add2(ull a, ull b) {
    ull r; asm("add.rn.f32x2 %0, %1, %2;" : "=l"(r) : "l"(a), "l"(b)); return r;
}
__device__ __forceinline__ ull mul2(ull a, ull b) {
    ull r; asm("mul.rn.f32x2 %0, %1, %2;" : "=l"(r) : "l"(a), "l"(b)); return r;
}
__device__ __forceinline__ ull fma2(ull a, ull b, ull c) {
    ull r; asm("fma.rn.f32x2 %0, %1, %2, %3;" : "=l"(r) : "l"(a), "l"(b), "l"(c)); return r;
}

// Taylor coeffs of erf(z)=z*P(z^2), pre-scaled by 1/sqrt(2):
// gelu(x) = z*(C + z*Ptilde(z^2)),  z = x/sqrt(2),  C = 1/sqrt(2)
#define EC0S  7.9788456080e-1f
#define EC1S -2.6596152027e-1f
#define EC2S  7.9788456080e-2f
#define EC3S -1.8997270260e-2f
#define EC4S  3.6939104237e-3f
#define EC5S -6.0446590722e-4f
#define EC6S  8.5244784915e-5f
#define EC7S -1.0554088026e-5f
#define CSQ2  7.0710678119e-1f

// ---------------- exact GELU (erf-based) for the cold path -------------------
__device__ __forceinline__ float gelu_exact(float x) {
    return 0.5f * x * (1.0f + erff(x * 0.70710678118654752f));
}

// ============ kernel A: proj + a/c of layer 0 (fused, k-split) ==============
__global__ void k_proj_ac(const float* __restrict__ nf,
                          const float* __restrict__ Wp,
                          const float* __restrict__ bp,
                          const float* __restrict__ Wm,
                          const float* __restrict__ bm) {
    int i0 = blockIdx.x * ACR;
    int d  = threadIdx.x;      // 0..127
    int ty = threadIdx.y;      // 0..3 k-slice / row id
    int tid = ty * DD + d;

    __shared__ float sh[ACR][DIN + 3];
    __shared__ float hn[ACR][DD];
    __shared__ float red[ACR][ACR][DD];   // [slice][row][d]

    for (int e = tid; e < ACR * DIN; e += ACR * DD) {
        int r = e / DIN, c = e % DIN;
        sh[r][c] = nf[(i0 + r) * DIN + c];
    }
    __syncthreads();

    // ---- proj GEMM, k-split over DIN ----
    {
        int k0 = (ty * DIN) / ACR, k1 = ((ty + 1) * DIN) / ACR;
        float acc[ACR] = {0.f, 0.f, 0.f, 0.f};
        for (int k = k0; k < k1; ++k) {
            float w = Wp[k * DD + d];
            #pragma unroll
            for (int r = 0; r < ACR; ++r) acc[r] = fmaf(sh[r][k], w, acc[r]);
        }
        #pragma unroll
        for (int r = 0; r < ACR; ++r) red[ty][r][d] = acc[r];
    }
    __syncthreads();
    {
        float h = bp[d] + red[0][ty][d] + red[1][ty][d] + red[2][ty][d] + red[3][ty][d];
        g_h[(i0 + ty) * DD + d] = h;
        hn[ty][d] = h;
    }
    __syncthreads();

    // ---- a/c GEMM for layer 0, k-split (32 per slice) ----
    const float* WA = Wm;               // layer 0
    const float* WC = Wm + DD * DD;
    float aa[ACR] = {0.f, 0.f, 0.f, 0.f};
    float cc[ACR] = {0.f, 0.f, 0.f, 0.f};
    int k0 = ty * 32;
    #pragma unroll 8
    for (int kk = 0; kk < 32; ++kk) {
        int k = k0 + kk;
        float wa = WA[k * DD + d];
        float wc = WC[k * DD + d];
        #pragma unroll
        for (int r = 0; r < ACR; ++r) {
            float hv = hn[r][k];
            aa[r] = fmaf(hv, wa, aa[r]);
            cc[r] = fmaf(hv, wc, cc[r]);
        }
    }
    #pragma unroll
    for (int r = 0; r < ACR; ++r) red[ty][r][d] = aa[r];
    __syncthreads();
    g_a[(i0 + ty) * DD + d] =
        (red[0][ty][d] + red[1][ty][d] + red[2][ty][d] + red[3][ty][d]) * CSQ2;
    __syncthreads();
    #pragma unroll
    for (int r = 0; r < ACR; ++r) red[ty][r][d] = cc[r];
    __syncthreads();
    g_cb[(i0 + ty) * DD + d] =
        (red[0][ty][d] + red[1][ty][d] + red[2][ty][d] + red[3][ty][d] + bm[d]) * CSQ2;
}

// ============ kernel B: agg (packed f32x2, 8-term scaled poly) ==============
// block (64,16) = 1024 threads, 64 regs/thread, 32 warps/SM, 147 blocks = 1 wave
__global__ __launch_bounds__(64 * YD, 1)
void k_agg(const float* __restrict__ adj) {
    int i0 = blockIdx.x * IPB;
    int rows = NN - i0; if (rows > IPB) rows = IPB;
    int t  = threadIdx.x;            // 0..63 d-pair index
    int ty = threadIdx.y;            // 0..YD-1
    int d2 = t * 2;

    ull K0 = pk2(EC0S, EC0S), K1 = pk2(EC1S, EC1S), K2 = pk2(EC2S, EC2S);
    ull K3 = pk2(EC3S, EC3S), K4 = pk2(EC4S, EC4S), K5 = pk2(EC5S, EC5S);
    ull K6 = pk2(EC6S, EC6S), K7 = pk2(EC7S, EC7S);
    ull KC = pk2(CSQ2, CSQ2);

    ull av2[IPB], acc[IPB];
    #pragma unroll
    for (int ii = 0; ii < IPB; ++ii) {
        av2[ii] = (ii < rows)
            ? *reinterpret_cast<const ull*>(&g_a[(i0 + ii) * DD + d2]) : 0ull;
        acc[ii] = 0ull;
    }

#define EVAL(ACC, AV, CV, AD) do {                                  \
        ull z = add2((AV), (CV));                                   \
        ull q = mul2(z, z);                                         \
        ull p = K7;                                                 \
        p = fma2(p, q, K6); p = fma2(p, q, K5); p = fma2(p, q, K4); \
        p = fma2(p, q, K3); p = fma2(p, q, K2); p = fma2(p, q, K1); \
        p = fma2(p, q, K0);                                         \
        ull u = fma2(z, p, KC);                                     \
        ull g = mul2(z, u);                                         \
        ull a2 = pk2((AD), (AD));                                   \
        (ACC) = fma2(a2, g, (ACC));                                 \
    } while (0)

    const int JC = NN / YD;          // 64 j per slice
    const int j0 = ty * JC;
    for (int j = j0; j < j0 + JC; j += 2) {
        ull cv0 = *reinterpret_cast<const ull*>(&g_cb[(j + 0) * DD + d2]);
        ull cv1 = *reinterpret_cast<const ull*>(&g_cb[(j + 1) * DD + d2]);
        #pragma unroll
        for (int ii = 0; ii < IPB; ++ii) {
            if (ii < rows) {
                float2 ad = *reinterpret_cast<const float2*>(
                    &adj[(size_t)(i0 + ii) * NN + j]);
                EVAL(acc[ii], av2[ii], cv0, ad.x);
                EVAL(acc[ii], av2[ii], cv1, ad.y);
            }
        }
    }
#undef EVAL

    // two-stage reduction: 16 -> 8 -> 1   (28KB static smem)
    __shared__ ull red[8][IPB][64];
    if (ty >= 8) {
        #pragma unroll
        for (int ii = 0; ii < IPB; ++ii) red[ty - 8][ii][t] = acc[ii];
    }
    __syncthreads();
    if (ty < 8) {
        #pragma unroll
        for (int ii = 0; ii < IPB; ++ii) acc[ii] = add2(acc[ii], red[ty][ii][t]);
    }
    __syncthreads();
    if (ty < 8) {
        #pragma unroll
        for (int ii = 0; ii < IPB; ++ii) red[ty][ii][t] = acc[ii];
    }
    __syncthreads();
    if (ty < rows) {
        int ii = ty;
        ull s = red[0][ii][t];
        #pragma unroll
        for (int p = 1; p < 8; ++p) s = add2(s, red[p][ii][t]);
        *reinterpret_cast<ull*>(&g_agg[(i0 + ii) * DD + d2]) = s;
    }
}

// ====== kernel C: update+LN (+ a/c of next layer) fused, k-split ============
__global__ void k_upac(const float* __restrict__ Wu,
                       const float* __restrict__ bu,
                       const float* __restrict__ gamma,
                       const float* __restrict__ beta,
                       const float* __restrict__ Wm,
                       const float* __restrict__ bm,
                       int l, int do_next) {
    int i0 = blockIdx.x * ACR;
    int d  = threadIdx.x;
    int ty = threadIdx.y;
    int tid = ty * DD + d;

    __shared__ float hsh[ACR][DD], ash[ACR][DD], newh[ACR][DD];
    __shared__ float red[ACR][ACR][DD];
    __shared__ float rs_m[ACR][4], rs_v[ACR][4];

    {   // 512 threads load 512 elements of each
        int r = tid >> 7, c = tid & 127;
        hsh[r][c] = g_h  [(i0 + r) * DD + c];
        ash[r][c] = g_agg[(i0 + r) * DD + c];
    }
    __syncthreads();

    // ---- update GEMM: k-slice of 32 ----
    const float* W1 = Wu + (size_t)l * 2 * DD * DD;
    const float* W2 = W1 + DD * DD;
    {
        float acc[ACR] = {0.f, 0.f, 0.f, 0.f};
        int k0 = ty * 32;
        #pragma unroll 8
        for (int kk = 0; kk < 32; ++kk) {
            int k = k0 + kk;
            float w1 = W1[k * DD + d];
            float w2 = W2[k * DD + d];
            #pragma unroll
            for (int r = 0; r < ACR; ++r) {
                acc[r] = fmaf(hsh[r][k], w1, acc[r]);
                acc[r] = fmaf(ash[r][k], w2, acc[r]);
            }
        }
        #pragma unroll
        for (int r = 0; r < ACR; ++r) red[ty][r][d] = acc[r];
    }
    __syncthreads();

    // each ty finalizes row r = ty
    int r = ty;
    float x = bu[l * DD + d]
            + red[0][r][d] + red[1][r][d] + red[2][r][d] + red[3][r][d];
    x = gelu_exact(x) + hsh[r][d];

    // ---- layernorm (128 d-threads of this ty = 4 warps) ----
    float v = x;
    #pragma unroll
    for (int o = 16; o > 0; o >>= 1) v += __shfl_xor_sync(0xffffffffu, v, o);
    if ((d & 31) == 0) rs_m[r][d >> 5] = v;
    __syncthreads();
    float mean = (rs_m[r][0] + rs_m[r][1] + rs_m[r][2] + rs_m[r][3]) * (1.0f / DD);
    float xm = x - mean;
    float v2 = xm * xm;
    #pragma unroll
    for (int o = 16; o > 0; o >>= 1) v2 += __shfl_xor_sync(0xffffffffu, v2, o);
    if ((d & 31) == 0) rs_v[r][d >> 5] = v2;
    __syncthreads();
    float var = (rs_v[r][0] + rs_v[r][1] + rs_v[r][2] + rs_v[r][3]) * (1.0f / DD);
    float y = xm * rsqrtf(var + 1e-5f) * gamma[l * DD + d] + beta[l * DD + d];
    g_h[(i0 + r) * DD + d] = y;
    newh[r][d] = y;
    __syncthreads();

    // ---- a/c GEMM for layer l+1 ----
    if (do_next) {
        const float* WA = Wm + (size_t)(l + 1) * 2 * DD * DD;
        const float* WC = WA + DD * DD;
        float aa[ACR] = {0.f, 0.f, 0.f, 0.f};
        float cc[ACR] = {0.f, 0.f, 0.f, 0.f};
        int k0 = ty * 32;
        #pragma unroll 8
        for (int kk = 0; kk < 32; ++kk) {
            int k = k0 + kk;
            float wa = WA[k * DD + d];
            float wc = WC[k * DD + d];
            #pragma unroll
            for (int rr = 0; rr < ACR; ++rr) {
                float hv = newh[rr][k];
                aa[rr] = fmaf(hv, wa, aa[rr]);
                cc[rr] = fmaf(hv, wc, cc[rr]);
            }
        }
        #pragma unroll
        for (int rr = 0; rr < ACR; ++rr) red[ty][rr][d] = aa[rr];
        __syncthreads();
        g_a[(i0 + ty) * DD + d] =
            (red[0][ty][d] + red[1][ty][d] + red[2][ty][d] + red[3][ty][d]) * CSQ2;
        __syncthreads();
        #pragma unroll
        for (int rr = 0; rr < ACR; ++rr) red[ty][rr][d] = cc[rr];
        __syncthreads();
        g_cb[(i0 + ty) * DD + d] =
            (red[0][ty][d] + red[1][ty][d] + red[2][ty][d] + red[3][ty][d]
             + bm[(l + 1) * DD + d]) * CSQ2;
    }
}

// ---------------- kernel D: output heads ------------------------------------
// out layout: threat[1024] | intent[1024*5] | action[1024*5] | h[1024*128]
__global__ void k_heads(const float* __restrict__ Wt,
                        const float* __restrict__ bt,
                        const float* __restrict__ Wi,
                        const float* __restrict__ bi,
                        const float* __restrict__ Wa,
                        const float* __restrict__ ba,
                        float* __restrict__ out) {
    int i = blockIdx.x;
    int d = threadIdx.x;
    __shared__ float hsh[DD];
    float hv = g_h[i * DD + d];
    hsh[d] = hv;
    __syncthreads();

    out[NN + NN * 5 + NN * 5 + i * DD + d] = hv;   // h copy

    if (d < 5) {
        float s = bi[d];
        #pragma unroll 8
        for (int k = 0; k < DD; ++k) s = fmaf(hsh[k], Wi[k * 5 + d], s);
        out[NN + i * 5 + d] = s;
        float s2 = ba[d];
        #pragma unroll 8
        for (int k = 0; k < DD; ++k) s2 = fmaf(hsh[k], Wa[k * 5 + d], s2);
        out[NN + NN * 5 + i * 5 + d] = s2;
    }
    if (d == 5) {
        float s = bt[0];
        #pragma unroll 8
        for (int k = 0; k < DD; ++k) s = fmaf(hsh[k], Wt[k], s);
        out[i] = 5.0f / (1.0f + expf(-s));
    }
}

// ---------------- launcher ---------------------------------------------------
extern "C" void kernel_launch(void* const* d_in, const int* in_sizes, int n_in,
                              void* d_out, int out_size) {
    const float* nf    = (const float*)d_in[0];
    const float* adj   = (const float*)d_in[1];
    const float* Wp    = (const float*)d_in[2];
    const float* bp    = (const float*)d_in[3];
    const float* Wm    = (const float*)d_in[4];
    const float* bm    = (const float*)d_in[5];
    const float* Wu    = (const float*)d_in[6];
    const float* bu    = (const float*)d_in[7];
    const float* gamma = (const float*)d_in[8];
    const float* beta  = (const float*)d_in[9];
    const float* Wt    = (const float*)d_in[10];
    const float* bt    = (const float*)d_in[11];
    const float* Wi    = (const float*)d_in[12];
    const float* bi    = (const float*)d_in[13];
    const float* Wa    = (const float*)d_in[14];
    const float* ba    = (const float*)d_in[15];
    float* out = (float*)d_out;

    dim3 gblk(DD, ACR);
    k_proj_ac<<<NN / ACR, gblk>>>(nf, Wp, bp, Wm, bm);
    for (int l = 0; l < NL; ++l) {
        dim3 ablk(64, YD);
        k_agg<<<(NN + IPB - 1) / IPB, ablk>>>(adj);
        k_upac<<<NN / ACR, gblk>>>(Wu, bu, gamma, beta, Wm, bm, l, (l + 1 < NL) ? 1 : 0);
    }
    k_heads<<<NN, DD>>>(Wt, bt, Wi, bi, Wa, ba, out);
}

// round 6
// speedup vs baseline: 1.1928x; 1.1928x over previous
#include <cuda_runtime.h>
#include <cuda_bf16.h>
#include <math.h>

// Problem constants
#define NN   1024
#define DD   128
#define DIN  137
#define NL   3
#define IPB  7      // i-rows per agg block (147 blocks = 1 wave on 148 SMs)
#define YD   8      // j-partitions per agg block (512-thread blocks)
#define ACR  4      // rows per block (and k-slices) in fused GEMM kernels

typedef unsigned long long ull;

// ---------------- scratch (device globals; no allocation allowed) -----------
__device__ float g_h  [NN * DD];
__device__ float g_a  [NN * DD];   // pre-scaled by 1/sqrt(2)
__device__ float g_cb [NN * DD];   // (c + bm) pre-scaled by 1/sqrt(2)
__device__ float g_agg[NN * DD];

// ---------------- packed f32x2 helpers --------------------------------------
__device__ __forceinline__ ull pk2(float a, float b) {
    ull r; asm("mov.b64 %0, {%1,%2};" : "=l"(r) : "f"(a), "f"(b)); return r;
}
__device__ __forceinline__ ull add2(ull a, ull b) {
    ull r; asm("add.rn.f32x2 %0, %1, %2;" : "=l"(r) : "l"(a), "l"(b)); return r;
}
__device__ __forceinline__ ull mul2(ull a, ull b) {
    ull r; asm("mul.rn.f32x2 %0, %1, %2;" : "=l"(r) : "l"(a), "l"(b)); return r;
}
__device__ __forceinline__ ull fma2(ull a, ull b, ull c) {
    ull r; asm("fma.rn.f32x2 %0, %1, %2, %3;" : "=l"(r) : "l"(a), "l"(b), "l"(c)); return r;
}

// Taylor coeffs of erf(z)=z*P(z^2), pre-scaled by 1/sqrt(2):
// gelu(x) = z*(C + z*Ptilde(z^2)),  z = x/sqrt(2),  C = 1/sqrt(2)
#define EC0S  7.9788456080e-1f
#define EC1S -2.6596152027e-1f
#define EC2S  7.9788456080e-2f
#define EC3S -1.8997270260e-2f
#define EC4S  3.6939104237e-3f
#define EC5S -6.0446590722e-4f
#define EC6S  8.5244784915e-5f
#define EC7S -1.0554088026e-5f
#define CSQ2  7.0710678119e-1f

// ---------------- exact GELU (erf-based) for the cold path -------------------
__device__ __forceinline__ float gelu_exact(float x) {
    return 0.5f * x * (1.0f + erff(x * 0.70710678118654752f));
}

// ============ kernel A: proj + a/c of layer 0 (fused, k-split) ==============
__global__ void k_proj_ac(const float* __restrict__ nf,
                          const float* __restrict__ Wp,
                          const float* __restrict__ bp,
                          const float* __restrict__ Wm,
                          const float* __restrict__ bm) {
    int i0 = blockIdx.x * ACR;
    int d  = threadIdx.x;      // 0..127
    int ty = threadIdx.y;      // 0..3 k-slice / row id
    int tid = ty * DD + d;

    __shared__ float sh[ACR][DIN + 3];
    __shared__ float hn[ACR][DD];
    __shared__ float red[ACR][ACR][DD];   // [slice][row][d]

    for (int e = tid; e < ACR * DIN; e += ACR * DD) {
        int r = e / DIN, c = e % DIN;
        sh[r][c] = nf[(i0 + r) * DIN + c];
    }
    __syncthreads();

    // ---- proj GEMM, k-split over DIN ----
    {
        int k0 = (ty * DIN) / ACR, k1 = ((ty + 1) * DIN) / ACR;
        float acc[ACR] = {0.f, 0.f, 0.f, 0.f};
        for (int k = k0; k < k1; ++k) {
            float w = Wp[k * DD + d];
            #pragma unroll
            for (int r = 0; r < ACR; ++r) acc[r] = fmaf(sh[r][k], w, acc[r]);
        }
        #pragma unroll
        for (int r = 0; r < ACR; ++r) red[ty][r][d] = acc[r];
    }
    __syncthreads();
    {
        float h = bp[d] + red[0][ty][d] + red[1][ty][d] + red[2][ty][d] + red[3][ty][d];
        g_h[(i0 + ty) * DD + d] = h;
        hn[ty][d] = h;
    }
    __syncthreads();

    // ---- a/c GEMM for layer 0, k-split (32 per slice) ----
    const float* WA = Wm;               // layer 0
    const float* WC = Wm + DD * DD;
    float aa[ACR] = {0.f, 0.f, 0.f, 0.f};
    float cc[ACR] = {0.f, 0.f, 0.f, 0.f};
    int k0 = ty * 32;
    #pragma unroll 8
    for (int kk = 0; kk < 32; ++kk) {
        int k = k0 + kk;
        float wa = WA[k * DD + d];
        float wc = WC[k * DD + d];
        #pragma unroll
        for (int r = 0; r < ACR; ++r) {
            float hv = hn[r][k];
            aa[r] = fmaf(hv, wa, aa[r]);
            cc[r] = fmaf(hv, wc, cc[r]);
        }
    }
    #pragma unroll
    for (int r = 0; r < ACR; ++r) red[ty][r][d] = aa[r];
    __syncthreads();
    g_a[(i0 + ty) * DD + d] =
        (red[0][ty][d] + red[1][ty][d] + red[2][ty][d] + red[3][ty][d]) * CSQ2;
    __syncthreads();
    #pragma unroll
    for (int r = 0; r < ACR; ++r) red[ty][r][d] = cc[r];
    __syncthreads();
    g_cb[(i0 + ty) * DD + d] =
        (red[0][ty][d] + red[1][ty][d] + red[2][ty][d] + red[3][ty][d] + bm[d]) * CSQ2;
}

// ============ kernel B: agg (packed f32x2, 8-term scaled poly) ==============
// R4 structure (512 threads, YD=8, float4 adj, j+=4) + 12-op EVAL
__global__ __launch_bounds__(64 * YD, 1)
void k_agg(const float* __restrict__ adj) {
    int i0 = blockIdx.x * IPB;
    int rows = NN - i0; if (rows > IPB) rows = IPB;
    int t  = threadIdx.x;            // 0..63 d-pair index
    int ty = threadIdx.y;            // 0..YD-1
    int d2 = t * 2;

    ull K0 = pk2(EC0S, EC0S), K1 = pk2(EC1S, EC1S), K2 = pk2(EC2S, EC2S);
    ull K3 = pk2(EC3S, EC3S), K4 = pk2(EC4S, EC4S), K5 = pk2(EC5S, EC5S);
    ull K6 = pk2(EC6S, EC6S), K7 = pk2(EC7S, EC7S);
    ull KC = pk2(CSQ2, CSQ2);

    ull av2[IPB], acc[IPB];
    #pragma unroll
    for (int ii = 0; ii < IPB; ++ii) {
        av2[ii] = (ii < rows)
            ? *reinterpret_cast<const ull*>(&g_a[(i0 + ii) * DD + d2]) : 0ull;
        acc[ii] = 0ull;
    }

#define EVAL(ACC, AV, CV, AD) do {                                  \
        ull z = add2((AV), (CV));                                   \
        ull q = mul2(z, z);                                         \
        ull p = K7;                                                 \
        p = fma2(p, q, K6); p = fma2(p, q, K5); p = fma2(p, q, K4); \
        p = fma2(p, q, K3); p = fma2(p, q, K2); p = fma2(p, q, K1); \
        p = fma2(p, q, K0);                                         \
        ull u = fma2(z, p, KC);                                     \
        ull g = mul2(z, u);                                         \
        ull a2 = pk2((AD), (AD));                                   \
        (ACC) = fma2(a2, g, (ACC));                                 \
    } while (0)

    const int JC = NN / YD;          // 128 j per slice
    const int j0 = ty * JC;
    for (int j = j0; j < j0 + JC; j += 4) {
        ull cv2[4];
        #pragma unroll
        for (int u = 0; u < 4; ++u)
            cv2[u] = *reinterpret_cast<const ull*>(&g_cb[(j + u) * DD + d2]);
        #pragma unroll
        for (int ii = 0; ii < IPB; ++ii) {
            if (ii < rows) {
                float4 ad = *reinterpret_cast<const float4*>(
                    &adj[(size_t)(i0 + ii) * NN + j]);
                EVAL(acc[ii], av2[ii], cv2[0], ad.x);
                EVAL(acc[ii], av2[ii], cv2[1], ad.y);
                EVAL(acc[ii], av2[ii], cv2[2], ad.z);
                EVAL(acc[ii], av2[ii], cv2[3], ad.w);
            }
        }
    }
#undef EVAL

    __shared__ ull red[YD][IPB][64];
    #pragma unroll
    for (int ii = 0; ii < IPB; ++ii) red[ty][ii][t] = acc[ii];
    __syncthreads();
    if (ty < rows) {
        int ii = ty;
        ull s = red[0][ii][t];
        #pragma unroll
        for (int p = 1; p < YD; ++p) s = add2(s, red[p][ii][t]);
        *reinterpret_cast<ull*>(&g_agg[(i0 + ii) * DD + d2]) = s;
    }
}

// ====== kernel C: update+LN (+ a/c of next layer) fused, k-split ============
__global__ void k_upac(const float* __restrict__ Wu,
                       const float* __restrict__ bu,
                       const float* __restrict__ gamma,
                       const float* __restrict__ beta,
                       const float* __restrict__ Wm,
                       const float* __restrict__ bm,
                       int l, int do_next) {
    int i0 = blockIdx.x * ACR;
    int d  = threadIdx.x;
    int ty = threadIdx.y;
    int tid = ty * DD + d;

    __shared__ float hsh[ACR][DD], ash[ACR][DD], newh[ACR][DD];
    __shared__ float red[ACR][ACR][DD];
    __shared__ float rs_m[ACR][4], rs_v[ACR][4];

    {   // 512 threads load 512 elements of each
        int r = tid >> 7, c = tid & 127;
        hsh[r][c] = g_h  [(i0 + r) * DD + c];
        ash[r][c] = g_agg[(i0 + r) * DD + c];
    }
    __syncthreads();

    // ---- update GEMM: k-slice of 32 ----
    const float* W1 = Wu + (size_t)l * 2 * DD * DD;
    const float* W2 = W1 + DD * DD;
    {
        float acc[ACR] = {0.f, 0.f, 0.f, 0.f};
        int k0 = ty * 32;
        #pragma unroll 8
        for (int kk = 0; kk < 32; ++kk) {
            int k = k0 + kk;
            float w1 = W1[k * DD + d];
            float w2 = W2[k * DD + d];
            #pragma unroll
            for (int r = 0; r < ACR; ++r) {
                acc[r] = fmaf(hsh[r][k], w1, acc[r]);
                acc[r] = fmaf(ash[r][k], w2, acc[r]);
            }
        }
        #pragma unroll
        for (int r = 0; r < ACR; ++r) red[ty][r][d] = acc[r];
    }
    __syncthreads();

    // each ty finalizes row r = ty
    int r = ty;
    float x = bu[l * DD + d]
            + red[0][r][d] + red[1][r][d] + red[2][r][d] + red[3][r][d];
    x = gelu_exact(x) + hsh[r][d];

    // ---- layernorm (128 d-threads of this ty = 4 warps) ----
    float v = x;
    #pragma unroll
    for (int o = 16; o > 0; o >>= 1) v += __shfl_xor_sync(0xffffffffu, v, o);
    if ((d & 31) == 0) rs_m[r][d >> 5] = v;
    __syncthreads();
    float mean = (rs_m[r][0] + rs_m[r][1] + rs_m[r][2] + rs_m[r][3]) * (1.0f / DD);
    float xm = x - mean;
    float v2 = xm * xm;
    #pragma unroll
    for (int o = 16; o > 0; o >>= 1) v2 += __shfl_xor_sync(0xffffffffu, v2, o);
    if ((d & 31) == 0) rs_v[r][d >> 5] = v2;
    __syncthreads();
    float var = (rs_v[r][0] + rs_v[r][1] + rs_v[r][2] + rs_v[r][3]) * (1.0f / DD);
    float y = xm * rsqrtf(var + 1e-5f) * gamma[l * DD + d] + beta[l * DD + d];
    g_h[(i0 + r) * DD + d] = y;
    newh[r][d] = y;
    __syncthreads();

    // ---- a/c GEMM for layer l+1 ----
    if (do_next) {
        const float* WA = Wm + (size_t)(l + 1) * 2 * DD * DD;
        const float* WC = WA + DD * DD;
        float aa[ACR] = {0.f, 0.f, 0.f, 0.f};
        float cc[ACR] = {0.f, 0.f, 0.f, 0.f};
        int k0 = ty * 32;
        #pragma unroll 8
        for (int kk = 0; kk < 32; ++kk) {
            int k = k0 + kk;
            float wa = WA[k * DD + d];
            float wc = WC[k * DD + d];
            #pragma unroll
            for (int rr = 0; rr < ACR; ++rr) {
                float hv = newh[rr][k];
                aa[rr] = fmaf(hv, wa, aa[rr]);
                cc[rr] = fmaf(hv, wc, cc[rr]);
            }
        }
        #pragma unroll
        for (int rr = 0; rr < ACR; ++rr) red[ty][rr][d] = aa[rr];
        __syncthreads();
        g_a[(i0 + ty) * DD + d] =
            (red[0][ty][d] + red[1][ty][d] + red[2][ty][d] + red[3][ty][d]) * CSQ2;
        __syncthreads();
        #pragma unroll
        for (int rr = 0; rr < ACR; ++rr) red[ty][rr][d] = cc[rr];
        __syncthreads();
        g_cb[(i0 + ty) * DD + d] =
            (red[0][ty][d] + red[1][ty][d] + red[2][ty][d] + red[3][ty][d]
             + bm[(l + 1) * DD + d]) * CSQ2;
    }
}

// ---------------- kernel D: output heads ------------------------------------
// out layout: threat[1024] | intent[1024*5] | action[1024*5] | h[1024*128]
__global__ void k_heads(const float* __restrict__ Wt,
                        const float* __restrict__ bt,
                        const float* __restrict__ Wi,
                        const float* __restrict__ bi,
                        const float* __restrict__ Wa,
                        const float* __restrict__ ba,
                        float* __restrict__ out) {
    int i = blockIdx.x;
    int d = threadIdx.x;
    __shared__ float hsh[DD];
    float hv = g_h[i * DD + d];
    hsh[d] = hv;
    __syncthreads();

    out[NN + NN * 5 + NN * 5 + i * DD + d] = hv;   // h copy

    if (d < 5) {
        float s = bi[d];
        #pragma unroll 8
        for (int k = 0; k < DD; ++k) s = fmaf(hsh[k], Wi[k * 5 + d], s);
        out[NN + i * 5 + d] = s;
        float s2 = ba[d];
        #pragma unroll 8
        for (int k = 0; k < DD; ++k) s2 = fmaf(hsh[k], Wa[k * 5 + d], s2);
        out[NN + NN * 5 + i * 5 + d] = s2;
    }
    if (d == 5) {
        float s = bt[0];
        #pragma unroll 8
        for (int k = 0; k < DD; ++k) s = fmaf(hsh[k], Wt[k], s);
        out[i] = 5.0f / (1.0f + expf(-s));
    }
}

// ---------------- launcher ---------------------------------------------------
extern "C" void kernel_launch(void* const* d_in, const int* in_sizes, int n_in,
                              void* d_out, int out_size) {
    const float* nf    = (const float*)d_in[0];
    const float* adj   = (const float*)d_in[1];
    const float* Wp    = (const float*)d_in[2];
    const float* bp    = (const float*)d_in[3];
    const float* Wm    = (const float*)d_in[4];
    const float* bm    = (const float*)d_in[5];
    const float* Wu    = (const float*)d_in[6];
    const float* bu    = (const float*)d_in[7];
    const float* gamma = (const float*)d_in[8];
    const float* beta  = (const float*)d_in[9];
    const float* Wt    = (const float*)d_in[10];
    const float* bt    = (const float*)d_in[11];
    const float* Wi    = (const float*)d_in[12];
    const float* bi    = (const float*)d_in[13];
    const float* Wa    = (const float*)d_in[14];
    const float* ba    = (const float*)d_in[15];
    float* out = (float*)d_out;

    dim3 gblk(DD, ACR);
    k_proj_ac<<<NN / ACR, gblk>>>(nf, Wp, bp, Wm, bm);
    for (int l = 0; l < NL; ++l) {
        dim3 ablk(64, YD);
        k_agg<<<(NN + IPB - 1) / IPB, ablk>>>(adj);
        k_upac<<<NN / ACR, gblk>>>(Wu, bu, gamma, beta, Wm, bm, l, (l + 1 < NL) ? 1 : 0);
    }
    k_heads<<<NN, DD>>>(Wt, bt, Wi, bi, Wa, ba, out);
}

// round 7
// speedup vs baseline: 1.3094x; 1.0977x over previous
#include <cuda_runtime.h>
#include <cuda_bf16.h>
#include <math.h>

// Problem constants
#define NN   1024
#define DD   128
#define DIN  137
#define NL   3
#define IPB  7      // i-rows per agg block (147 blocks = 1 wave on 148 SMs)
#define YD   8      // j-partitions per agg block (512-thread blocks)
#define ACR  4      // rows per block (and k-slices) in fused GEMM kernels

typedef unsigned long long ull;

// ---------------- scratch (device globals; no allocation allowed) -----------
__device__ float g_h  [NN * DD];
__device__ float g_a  [NN * DD];   // pre-scaled by 1/sqrt(2)
__device__ float g_cb [NN * DD];   // (c + bm) pre-scaled by 1/sqrt(2)
__device__ float g_agg[NN * DD];

// ---------------- packed f32x2 helpers --------------------------------------
__device__ __forceinline__ ull pk2(float a, float b) {
    ull r; asm("mov.b64 %0, {%1,%2};" : "=l"(r) : "f"(a), "f"(b)); return r;
}
__device__ __forceinline__ ull add2(ull a, ull b) {
    ull r; asm("add.rn.f32x2 %0, %1, %2;" : "=l"(r) : "l"(a), "l"(b)); return r;
}
__device__ __forceinline__ ull mul2(ull a, ull b) {
    ull r; asm("mul.rn.f32x2 %0, %1, %2;" : "=l"(r) : "l"(a), "l"(b)); return r;
}
__device__ __forceinline__ ull fma2(ull a, ull b, ull c) {
    ull r; asm("fma.rn.f32x2 %0, %1, %2, %3;" : "=l"(r) : "l"(a), "l"(b), "l"(c)); return r;
}

// Taylor coeffs of erf(z)=z*P(z^2), pre-scaled by 1/sqrt(2):
// gelu(x) = z*(C + z*Ptilde(z^2)),  z = x/sqrt(2),  C = 1/sqrt(2)
#define EC0S  7.9788456080e-1f
#define EC1S -2.6596152027e-1f
#define EC2S  7.9788456080e-2f
#define EC3S -1.8997270260e-2f
#define EC4S  3.6939104237e-3f
#define EC5S -6.0446590722e-4f
#define CSQ2  7.0710678119e-1f

// ---------------- exact GELU (erf-based) for the cold path -------------------
__device__ __forceinline__ float gelu_exact(float x) {
    return 0.5f * x * (1.0f + erff(x * 0.70710678118654752f));
}

// ============ kernel A: proj + a/c of layer 0 (fused, k-split) ==============
__global__ void k_proj_ac(const float* __restrict__ nf,
                          const float* __restrict__ Wp,
                          const float* __restrict__ bp,
                          const float* __restrict__ Wm,
                          const float* __restrict__ bm) {
    int i0 = blockIdx.x * ACR;
    int d  = threadIdx.x;      // 0..127
    int ty = threadIdx.y;      // 0..3 k-slice / row id
    int tid = ty * DD + d;

    __shared__ float sh[ACR][DIN + 3];
    __shared__ float hn[ACR][DD];
    __shared__ float red[ACR][ACR][DD];   // [slice][row][d]

    for (int e = tid; e < ACR * DIN; e += ACR * DD) {
        int r = e / DIN, c = e % DIN;
        sh[r][c] = nf[(i0 + r) * DIN + c];
    }
    __syncthreads();

    // ---- proj GEMM, k-split over DIN ----
    {
        int k0 = (ty * DIN) / ACR, k1 = ((ty + 1) * DIN) / ACR;
        float acc[ACR] = {0.f, 0.f, 0.f, 0.f};
        for (int k = k0; k < k1; ++k) {
            float w = Wp[k * DD + d];
            #pragma unroll
            for (int r = 0; r < ACR; ++r) acc[r] = fmaf(sh[r][k], w, acc[r]);
        }
        #pragma unroll
        for (int r = 0; r < ACR; ++r) red[ty][r][d] = acc[r];
    }
    __syncthreads();
    {
        float h = bp[d] + red[0][ty][d] + red[1][ty][d] + red[2][ty][d] + red[3][ty][d];
        g_h[(i0 + ty) * DD + d] = h;
        hn[ty][d] = h;
    }
    __syncthreads();

    // ---- a/c GEMM for layer 0, k-split (32 per slice) ----
    const float* WA = Wm;               // layer 0
    const float* WC = Wm + DD * DD;
    float aa[ACR] = {0.f, 0.f, 0.f, 0.f};
    float cc[ACR] = {0.f, 0.f, 0.f, 0.f};
    int k0 = ty * 32;
    #pragma unroll 8
    for (int kk = 0; kk < 32; ++kk) {
        int k = k0 + kk;
        float wa = WA[k * DD + d];
        float wc = WC[k * DD + d];
        #pragma unroll
        for (int r = 0; r < ACR; ++r) {
            float hv = hn[r][k];
            aa[r] = fmaf(hv, wa, aa[r]);
            cc[r] = fmaf(hv, wc, cc[r]);
        }
    }
    #pragma unroll
    for (int r = 0; r < ACR; ++r) red[ty][r][d] = aa[r];
    __syncthreads();
    g_a[(i0 + ty) * DD + d] =
        (red[0][ty][d] + red[1][ty][d] + red[2][ty][d] + red[3][ty][d]) * CSQ2;
    __syncthreads();
    #pragma unroll
    for (int r = 0; r < ACR; ++r) red[ty][r][d] = cc[r];
    __syncthreads();
    g_cb[(i0 + ty) * DD + d] =
        (red[0][ty][d] + red[1][ty][d] + red[2][ty][d] + red[3][ty][d] + bm[d]) * CSQ2;
}

// ============ kernel B: agg (packed f32x2, 6-term scaled poly) ==============
// R6 structure (512 threads, YD=8, float4 adj, j+=4), 10-op EVAL
__global__ __launch_bounds__(64 * YD, 1)
void k_agg(const float* __restrict__ adj) {
    int i0 = blockIdx.x * IPB;
    int rows = NN - i0; if (rows > IPB) rows = IPB;
    int t  = threadIdx.x;            // 0..63 d-pair index
    int ty = threadIdx.y;            // 0..YD-1
    int d2 = t * 2;

    ull K0 = pk2(EC0S, EC0S), K1 = pk2(EC1S, EC1S), K2 = pk2(EC2S, EC2S);
    ull K3 = pk2(EC3S, EC3S), K4 = pk2(EC4S, EC4S), K5 = pk2(EC5S, EC5S);
    ull KC = pk2(CSQ2, CSQ2);

    ull av2[IPB], acc[IPB];
    #pragma unroll
    for (int ii = 0; ii < IPB; ++ii) {
        av2[ii] = (ii < rows)
            ? *reinterpret_cast<const ull*>(&g_a[(i0 + ii) * DD + d2]) : 0ull;
        acc[ii] = 0ull;
    }

#define EVAL(ACC, AV, CV, AD) do {                                  \
        ull z = add2((AV), (CV));                                   \
        ull q = mul2(z, z);                                         \
        ull p = K5;                                                 \
        p = fma2(p, q, K4); p = fma2(p, q, K3); p = fma2(p, q, K2); \
        p = fma2(p, q, K1); p = fma2(p, q, K0);                     \
        ull u = fma2(z, p, KC);                                     \
        ull g = mul2(z, u);                                         \
        ull a2 = pk2((AD), (AD));                                   \
        (ACC) = fma2(a2, g, (ACC));                                 \
    } while (0)

    const int JC = NN / YD;          // 128 j per slice
    const int j0 = ty * JC;
    for (int j = j0; j < j0 + JC; j += 4) {
        ull cv2[4];
        #pragma unroll
        for (int u = 0; u < 4; ++u)
            cv2[u] = *reinterpret_cast<const ull*>(&g_cb[(j + u) * DD + d2]);
        #pragma unroll
        for (int ii = 0; ii < IPB; ++ii) {
            if (ii < rows) {
                float4 ad = *reinterpret_cast<const float4*>(
                    &adj[(size_t)(i0 + ii) * NN + j]);
                EVAL(acc[ii], av2[ii], cv2[0], ad.x);
                EVAL(acc[ii], av2[ii], cv2[1], ad.y);
                EVAL(acc[ii], av2[ii], cv2[2], ad.z);
                EVAL(acc[ii], av2[ii], cv2[3], ad.w);
            }
        }
    }
#undef EVAL

    __shared__ ull red[YD][IPB][64];
    #pragma unroll
    for (int ii = 0; ii < IPB; ++ii) red[ty][ii][t] = acc[ii];
    __syncthreads();
    if (ty < rows) {
        int ii = ty;
        ull s = red[0][ii][t];
        #pragma unroll
        for (int p = 1; p < YD; ++p) s = add2(s, red[p][ii][t]);
        *reinterpret_cast<ull*>(&g_agg[(i0 + ii) * DD + d2]) = s;
    }
}

// ====== kernel C: update+LN (+ a/c of next layer) fused, k-split ============
__global__ void k_upac(const float* __restrict__ Wu,
                       const float* __restrict__ bu,
                       const float* __restrict__ gamma,
                       const float* __restrict__ beta,
                       const float* __restrict__ Wm,
                       const float* __restrict__ bm,
                       int l, int do_next) {
    int i0 = blockIdx.x * ACR;
    int d  = threadIdx.x;
    int ty = threadIdx.y;
    int tid = ty * DD + d;

    __shared__ float hsh[ACR][DD], ash[ACR][DD], newh[ACR][DD];
    __shared__ float red[ACR][ACR][DD];
    __shared__ float rs_m[ACR][4], rs_v[ACR][4];

    {   // 512 threads load 512 elements of each
        int r = tid >> 7, c = tid & 127;
        hsh[r][c] = g_h  [(i0 + r) * DD + c];
        ash[r][c] = g_agg[(i0 + r) * DD + c];
    }
    __syncthreads();

    // ---- update GEMM: k-slice of 32 ----
    const float* W1 = Wu + (size_t)l * 2 * DD * DD;
    const float* W2 = W1 + DD * DD;
    {
        float acc[ACR] = {0.f, 0.f, 0.f, 0.f};
        int k0 = ty * 32;
        #pragma unroll 8
        for (int kk = 0; kk < 32; ++kk) {
            int k = k0 + kk;
            float w1 = W1[k * DD + d];
            float w2 = W2[k * DD + d];
            #pragma unroll
            for (int r = 0; r < ACR; ++r) {
                acc[r] = fmaf(hsh[r][k], w1, acc[r]);
                acc[r] = fmaf(ash[r][k], w2, acc[r]);
            }
        }
        #pragma unroll
        for (int r = 0; r < ACR; ++r) red[ty][r][d] = acc[r];
    }
    __syncthreads();

    // each ty finalizes row r = ty
    int r = ty;
    float x = bu[l * DD + d]
            + red[0][r][d] + red[1][r][d] + red[2][r][d] + red[3][r][d];
    x = gelu_exact(x) + hsh[r][d];

    // ---- layernorm (128 d-threads of this ty = 4 warps) ----
    float v = x;
    #pragma unroll
    for (int o = 16; o > 0; o >>= 1) v += __shfl_xor_sync(0xffffffffu, v, o);
    if ((d & 31) == 0) rs_m[r][d >> 5] = v;
    __syncthreads();
    float mean = (rs_m[r][0] + rs_m[r][1] + rs_m[r][2] + rs_m[r][3]) * (1.0f / DD);
    float xm = x - mean;
    float v2 = xm * xm;
    #pragma unroll
    for (int o = 16; o > 0; o >>= 1) v2 += __shfl_xor_sync(0xffffffffu, v2, o);
    if ((d & 31) == 0) rs_v[r][d >> 5] = v2;
    __syncthreads();
    float var = (rs_v[r][0] + rs_v[r][1] + rs_v[r][2] + rs_v[r][3]) * (1.0f / DD);
    float y = xm * rsqrtf(var + 1e-5f) * gamma[l * DD + d] + beta[l * DD + d];
    g_h[(i0 + r) * DD + d] = y;
    newh[r][d] = y;
    __syncthreads();

    // ---- a/c GEMM for layer l+1 ----
    if (do_next) {
        const float* WA = Wm + (size_t)(l + 1) * 2 * DD * DD;
        const float* WC = WA + DD * DD;
        float aa[ACR] = {0.f, 0.f, 0.f, 0.f};
        float cc[ACR] = {0.f, 0.f, 0.f, 0.f};
        int k0 = ty * 32;
        #pragma unroll 8
        for (int kk = 0; kk < 32; ++kk) {
            int k = k0 + kk;
            float wa = WA[k * DD + d];
            float wc = WC[k * DD + d];
            #pragma unroll
            for (int rr = 0; rr < ACR; ++rr) {
                float hv = newh[rr][k];
                aa[rr] = fmaf(hv, wa, aa[rr]);
                cc[rr] = fmaf(hv, wc, cc[rr]);
            }
        }
        #pragma unroll
        for (int rr = 0; rr < ACR; ++rr) red[ty][rr][d] = aa[rr];
        __syncthreads();
        g_a[(i0 + ty) * DD + d] =
            (red[0][ty][d] + red[1][ty][d] + red[2][ty][d] + red[3][ty][d]) * CSQ2;
        __syncthreads();
        #pragma unroll
        for (int rr = 0; rr < ACR; ++rr) red[ty][rr][d] = cc[rr];
        __syncthreads();
        g_cb[(i0 + ty) * DD + d] =
            (red[0][ty][d] + red[1][ty][d] + red[2][ty][d] + red[3][ty][d]
             + bm[(l + 1) * DD + d]) * CSQ2;
    }
}

// ---------------- kernel D: output heads ------------------------------------
// out layout: threat[1024] | intent[1024*5] | action[1024*5] | h[1024*128]
__global__ void k_heads(const float* __restrict__ Wt,
                        const float* __restrict__ bt,
                        const float* __restrict__ Wi,
                        const float* __restrict__ bi,
                        const float* __restrict__ Wa,
                        const float* __restrict__ ba,
                        float* __restrict__ out) {
    int i = blockIdx.x;
    int d = threadIdx.x;
    __shared__ float hsh[DD];
    float hv = g_h[i * DD + d];
    hsh[d] = hv;
    __syncthreads();

    out[NN + NN * 5 + NN * 5 + i * DD + d] = hv;   // h copy

    if (d < 5) {
        float s = bi[d];
        #pragma unroll 8
        for (int k = 0; k < DD; ++k) s = fmaf(hsh[k], Wi[k * 5 + d], s);
        out[NN + i * 5 + d] = s;
        float s2 = ba[d];
        #pragma unroll 8
        for (int k = 0; k < DD; ++k) s2 = fmaf(hsh[k], Wa[k * 5 + d], s2);
        out[NN + NN * 5 + i * 5 + d] = s2;
    }
    if (d == 5) {
        float s = bt[0];
        #pragma unroll 8
        for (int k = 0; k < DD; ++k) s = fmaf(hsh[k], Wt[k], s);
        out[i] = 5.0f / (1.0f + expf(-s));
    }
}

// ---------------- launcher ---------------------------------------------------
extern "C" void kernel_launch(void* const* d_in, const int* in_sizes, int n_in,
                              void* d_out, int out_size) {
    const float* nf    = (const float*)d_in[0];
    const float* adj   = (const float*)d_in[1];
    const float* Wp    = (const float*)d_in[2];
    const float* bp    = (const float*)d_in[3];
    const float* Wm    = (const float*)d_in[4];
    const float* bm    = (const float*)d_in[5];
    const float* Wu    = (const float*)d_in[6];
    const float* bu    = (const float*)d_in[7];
    const float* gamma = (const float*)d_in[8];
    const float* beta  = (const float*)d_in[9];
    const float* Wt    = (const float*)d_in[10];
    const float* bt    = (const float*)d_in[11];
    const float* Wi    = (const float*)d_in[12];
    const float* bi    = (const float*)d_in[13];
    const float* Wa    = (const float*)d_in[14];
    const float* ba    = (const float*)d_in[15];
    float* out = (float*)d_out;

    dim3 gblk(DD, ACR);
    k_proj_ac<<<NN / ACR, gblk>>>(nf, Wp, bp, Wm, bm);
    for (int l = 0; l < NL; ++l) {
        dim3 ablk(64, YD);
        k_agg<<<(NN + IPB - 1) / IPB, ablk>>>(adj);
        k_upac<<<NN / ACR, gblk>>>(Wu, bu, gamma, beta, Wm, bm, l, (l + 1 < NL) ? 1 : 0);
    }
    k_heads<<<NN, DD>>>(Wt, bt, Wi, bi, Wa, ba, out);
}

// round 9
// speedup vs baseline: 1.3422x; 1.0250x over previous
#include <cuda_runtime.h>
#include <cuda_bf16.h>
#include <math.h>

// Problem constants
#define NN   1024
#define DD   128
#define DIN  137
#define NL   3
#define IPB  7      // i-rows per agg block (147 blocks = 1 wave on 148 SMs)
#define YD   8      // j-partitions per agg block (512-thread blocks)
#define ACR  4      // rows per block (and k-slices) in fused GEMM kernels

typedef unsigned long long ull;

// ---------------- scratch (device globals; no allocation allowed) -----------
__device__ float g_h  [NN * DD];
__device__ float g_a  [NN * DD];   // pre-scaled by 1/sqrt(2)
__device__ float g_cb [NN * DD];   // (c + bm) pre-scaled by 1/sqrt(2)
__device__ float g_agg[NN * DD];

// ---------------- packed f32x2 helpers --------------------------------------
__device__ __forceinline__ ull pk2(float a, float b) {
    ull r; asm("mov.b64 %0, {%1,%2};" : "=l"(r) : "f"(a), "f"(b)); return r;
}
__device__ __forceinline__ ull add2(ull a, ull b) {
    ull r; asm("add.rn.f32x2 %0, %1, %2;" : "=l"(r) : "l"(a), "l"(b)); return r;
}
__device__ __forceinline__ ull mul2(ull a, ull b) {
    ull r; asm("mul.rn.f32x2 %0, %1, %2;" : "=l"(r) : "l"(a), "l"(b)); return r;
}
__device__ __forceinline__ ull fma2(ull a, ull b, ull c) {
    ull r; asm("fma.rn.f32x2 %0, %1, %2, %3;" : "=l"(r) : "l"(a), "l"(b), "l"(c)); return r;
}

// Taylor coeffs of erf(z)=z*P(z^2), pre-scaled by 1/sqrt(2):
// gelu(x) = z*(C + z*Ptilde(z^2)),  z = x/sqrt(2),  C = 1/sqrt(2)
#define EC0S  7.9788456080e-1f
#define EC1S -2.6596152027e-1f
#define EC2S  7.9788456080e-2f
#define EC3S -1.8997270260e-2f
#define EC4S  3.6939104237e-3f
#define EC5S -6.0446590722e-4f
#define CSQ2  7.0710678119e-1f

// ---------------- exact GELU (erf-based) for the cold path -------------------
__device__ __forceinline__ float gelu_exact(float x) {
    return 0.5f * x * (1.0f + erff(x * 0.70710678118654752f));
}

// ============ kernel A: proj + a/c of layer 0 (fused, k-split) ==============
__global__ void k_proj_ac(const float* __restrict__ nf,
                          const float* __restrict__ Wp,
                          const float* __restrict__ bp,
                          const float* __restrict__ Wm,
                          const float* __restrict__ bm) {
    int i0 = blockIdx.x * ACR;
    int d  = threadIdx.x;      // 0..127
    int ty = threadIdx.y;      // 0..3 k-slice / row id
    int tid = ty * DD + d;

    __shared__ float sh[ACR][DIN + 3];
    __shared__ float hn[ACR][DD];
    __shared__ float red[ACR][ACR][DD];   // [slice][row][d]

    for (int e = tid; e < ACR * DIN; e += ACR * DD) {
        int r = e / DIN, c = e % DIN;
        sh[r][c] = nf[(i0 + r) * DIN + c];
    }
    __syncthreads();

    // ---- proj GEMM, k-split over DIN ----
    {
        int k0 = (ty * DIN) / ACR, k1 = ((ty + 1) * DIN) / ACR;
        float acc[ACR] = {0.f, 0.f, 0.f, 0.f};
        for (int k = k0; k < k1; ++k) {
            float w = Wp[k * DD + d];
            #pragma unroll
            for (int r = 0; r < ACR; ++r) acc[r] = fmaf(sh[r][k], w, acc[r]);
        }
        #pragma unroll
        for (int r = 0; r < ACR; ++r) red[ty][r][d] = acc[r];
    }
    __syncthreads();
    {
        float h = bp[d] + red[0][ty][d] + red[1][ty][d] + red[2][ty][d] + red[3][ty][d];
        g_h[(i0 + ty) * DD + d] = h;
        hn[ty][d] = h;
    }
    __syncthreads();

    // ---- a/c GEMM for layer 0, k-split (32 per slice) ----
    const float* WA = Wm;               // layer 0
    const float* WC = Wm + DD * DD;
    float aa[ACR] = {0.f, 0.f, 0.f, 0.f};
    float cc[ACR] = {0.f, 0.f, 0.f, 0.f};
    int k0 = ty * 32;
    #pragma unroll 8
    for (int kk = 0; kk < 32; ++kk) {
        int k = k0 + kk;
        float wa = WA[k * DD + d];
        float wc = WC[k * DD + d];
        #pragma unroll
        for (int r = 0; r < ACR; ++r) {
            float hv = hn[r][k];
            aa[r] = fmaf(hv, wa, aa[r]);
            cc[r] = fmaf(hv, wc, cc[r]);
        }
    }
    #pragma unroll
    for (int r = 0; r < ACR; ++r) red[ty][r][d] = aa[r];
    __syncthreads();
    g_a[(i0 + ty) * DD + d] =
        (red[0][ty][d] + red[1][ty][d] + red[2][ty][d] + red[3][ty][d]) * CSQ2;
    __syncthreads();
    #pragma unroll
    for (int r = 0; r < ACR; ++r) red[ty][r][d] = cc[r];
    __syncthreads();
    g_cb[(i0 + ty) * DD + d] =
        (red[0][ty][d] + red[1][ty][d] + red[2][ty][d] + red[3][ty][d] + bm[d]) * CSQ2;
}

// ============ kernel B: agg (packed f32x2, 6-term scaled poly) ==============
// smem-staged adj tile + double-buffered cb loads; 10-op EVAL
__global__ __launch_bounds__(64 * YD, 1)
void k_agg(const float* __restrict__ adj) {
    int i0 = blockIdx.x * IPB;
    int rows = NN - i0; if (rows > IPB) rows = IPB;
    int t  = threadIdx.x;            // 0..63 d-pair index
    int ty = threadIdx.y;            // 0..YD-1
    int d2 = t * 2;
    int tid = ty * 64 + t;

    // 28,672 B buffer: adj tile during mainloop, reduction scratch after
    __shared__ __align__(16) char smbuf[IPB * NN * 4];
    float* s_adj = (float*)smbuf;

    // ---- stage adj tile: IPB rows x 1024 floats, coalesced float4 ----
    {
        float4* dst = (float4*)s_adj;
        for (int e = tid; e < IPB * (NN / 4); e += 64 * YD) {
            int r = e >> 8;                  // /256
            int c4 = e & 255;
            if (r < rows)
                dst[r * (NN / 4) + c4] =
                    ((const float4*)&adj[(size_t)(i0 + r) * NN])[c4];
        }
    }

    ull K0 = pk2(EC0S, EC0S), K1 = pk2(EC1S, EC1S), K2 = pk2(EC2S, EC2S);
    ull K3 = pk2(EC3S, EC3S), K4 = pk2(EC4S, EC4S), K5 = pk2(EC5S, EC5S);
    ull KC = pk2(CSQ2, CSQ2);

    ull av2[IPB], acc[IPB];
    #pragma unroll
    for (int ii = 0; ii < IPB; ++ii) {
        av2[ii] = (ii < rows)
            ? *reinterpret_cast<const ull*>(&g_a[(i0 + ii) * DD + d2]) : 0ull;
        acc[ii] = 0ull;
    }
    __syncthreads();   // adj tile ready

#define EVAL(ACC, AV, CV, AD) do {                                  \
        ull z = add2((AV), (CV));                                   \
        ull q = mul2(z, z);                                         \
        ull p = K5;                                                 \
        p = fma2(p, q, K4); p = fma2(p, q, K3); p = fma2(p, q, K2); \
        p = fma2(p, q, K1); p = fma2(p, q, K0);                     \
        ull u = fma2(z, p, KC);                                     \
        ull g = mul2(z, u);                                         \
        ull a2 = pk2((AD), (AD));                                   \
        (ACC) = fma2(a2, g, (ACC));                                 \
    } while (0)

    const int JC = NN / YD;          // 128 j per slice
    const int j0 = ty * JC;

    // prologue: load first cb group
    ull cv2[4], cvn[4];
    #pragma unroll
    for (int u = 0; u < 4; ++u)
        cv2[u] = *reinterpret_cast<const ull*>(&g_cb[(j0 + u) * DD + d2]);

    for (int j = j0; j < j0 + JC; j += 4) {
        // prefetch next group's cb (wraps to j0 on last iter; values unused)
        int jn = (j + 4 < j0 + JC) ? (j + 4) : j0;
        #pragma unroll
        for (int u = 0; u < 4; ++u)
            cvn[u] = *reinterpret_cast<const ull*>(&g_cb[(jn + u) * DD + d2]);

        #pragma unroll
        for (int ii = 0; ii < IPB; ++ii) {
            if (ii < rows) {
                float4 ad = *reinterpret_cast<const float4*>(&s_adj[ii * NN + j]);
                EVAL(acc[ii], av2[ii], cv2[0], ad.x);
                EVAL(acc[ii], av2[ii], cv2[1], ad.y);
                EVAL(acc[ii], av2[ii], cv2[2], ad.z);
                EVAL(acc[ii], av2[ii], cv2[3], ad.w);
            }
        }
        #pragma unroll
        for (int u = 0; u < 4; ++u) cv2[u] = cvn[u];
    }
#undef EVAL

    __syncthreads();   // all adj reads done; reuse smbuf for reduction
    ull (*red)[IPB][64] = (ull (*)[IPB][64])smbuf;
    #pragma unroll
    for (int ii = 0; ii < IPB; ++ii) red[ty][ii][t] = acc[ii];
    __syncthreads();
    if (ty < rows) {
        int ii = ty;
        ull s = red[0][ii][t];
        #pragma unroll
        for (int p = 1; p < YD; ++p) s = add2(s, red[p][ii][t]);
        *reinterpret_cast<ull*>(&g_agg[(i0 + ii) * DD + d2]) = s;
    }
}

// ====== kernel C: update+LN (+ a/c of next layer) fused, k-split ============
__global__ void k_upac(const float* __restrict__ Wu,
                       const float* __restrict__ bu,
                       const float* __restrict__ gamma,
                       const float* __restrict__ beta,
                       const float* __restrict__ Wm,
                       const float* __restrict__ bm,
                       int l, int do_next) {
    int i0 = blockIdx.x * ACR;
    int d  = threadIdx.x;
    int ty = threadIdx.y;
    int tid = ty * DD + d;

    __shared__ float hsh[ACR][DD], ash[ACR][DD], newh[ACR][DD];
    __shared__ float red[ACR][ACR][DD];
    __shared__ float rs_m[ACR][4], rs_v[ACR][4];

    {   // 512 threads load 512 elements of each
        int r = tid >> 7, c = tid & 127;
        hsh[r][c] = g_h  [(i0 + r) * DD + c];
        ash[r][c] = g_agg[(i0 + r) * DD + c];
    }
    __syncthreads();

    // ---- update GEMM: k-slice of 32 ----
    const float* W1 = Wu + (size_t)l * 2 * DD * DD;
    const float* W2 = W1 + DD * DD;
    {
        float acc[ACR] = {0.f, 0.f, 0.f, 0.f};
        int k0 = ty * 32;
        #pragma unroll 8
        for (int kk = 0; kk < 32; ++kk) {
            int k = k0 + kk;
            float w1 = W1[k * DD + d];
            float w2 = W2[k * DD + d];
            #pragma unroll
            for (int r = 0; r < ACR; ++r) {
                acc[r] = fmaf(hsh[r][k], w1, acc[r]);
                acc[r] = fmaf(ash[r][k], w2, acc[r]);
            }
        }
        #pragma unroll
        for (int r = 0; r < ACR; ++r) red[ty][r][d] = acc[r];
    }
    __syncthreads();

    // each ty finalizes row r = ty
    int r = ty;
    float x = bu[l * DD + d]
            + red[0][r][d] + red[1][r][d] + red[2][r][d] + red[3][r][d];
    x = gelu_exact(x) + hsh[r][d];

    // ---- layernorm (128 d-threads of this ty = 4 warps) ----
    float v = x;
    #pragma unroll
    for (int o = 16; o > 0; o >>= 1) v += __shfl_xor_sync(0xffffffffu, v, o);
    if ((d & 31) == 0) rs_m[r][d >> 5] = v;
    __syncthreads();
    float mean = (rs_m[r][0] + rs_m[r][1] + rs_m[r][2] + rs_m[r][3]) * (1.0f / DD);
    float xm = x - mean;
    float v2 = xm * xm;
    #pragma unroll
    for (int o = 16; o > 0; o >>= 1) v2 += __shfl_xor_sync(0xffffffffu, v2, o);
    if ((d & 31) == 0) rs_v[r][d >> 5] = v2;
    __syncthreads();
    float var = (rs_v[r][0] + rs_v[r][1] + rs_v[r][2] + rs_v[r][3]) * (1.0f / DD);
    float y = xm * rsqrtf(var + 1e-5f) * gamma[l * DD + d] + beta[l * DD + d];
    g_h[(i0 + r) * DD + d] = y;
    newh[r][d] = y;
    __syncthreads();

    // ---- a/c GEMM for layer l+1 ----
    if (do_next) {
        const float* WA = Wm + (size_t)(l + 1) * 2 * DD * DD;
        const float* WC = WA + DD * DD;
        float aa[ACR] = {0.f, 0.f, 0.f, 0.f};
        float cc[ACR] = {0.f, 0.f, 0.f, 0.f};
        int k0 = ty * 32;
        #pragma unroll 8
        for (int kk = 0; kk < 32; ++kk) {
            int k = k0 + kk;
            float wa = WA[k * DD + d];
            float wc = WC[k * DD + d];
            #pragma unroll
            for (int rr = 0; rr < ACR; ++rr) {
                float hv = newh[rr][k];
                aa[rr] = fmaf(hv, wa, aa[rr]);
                cc[rr] = fmaf(hv, wc, cc[rr]);
            }
        }
        #pragma unroll
        for (int rr = 0; rr < ACR; ++rr) red[ty][rr][d] = aa[rr];
        __syncthreads();
        g_a[(i0 + ty) * DD + d] =
            (red[0][ty][d] + red[1][ty][d] + red[2][ty][d] + red[3][ty][d]) * CSQ2;
        __syncthreads();
        #pragma unroll
        for (int rr = 0; rr < ACR; ++rr) red[ty][rr][d] = cc[rr];
        __syncthreads();
        g_cb[(i0 + ty) * DD + d] =
            (red[0][ty][d] + red[1][ty][d] + red[2][ty][d] + red[3][ty][d]
             + bm[(l + 1) * DD + d]) * CSQ2;
    }
}

// ---------------- kernel D: output heads ------------------------------------
// out layout: threat[1024] | intent[1024*5] | action[1024*5] | h[1024*128]
__global__ void k_heads(const float* __restrict__ Wt,
                        const float* __restrict__ bt,
                        const float* __restrict__ Wi,
                        const float* __restrict__ bi,
                        const float* __restrict__ Wa,
                        const float* __restrict__ ba,
                        float* __restrict__ out) {
    int i = blockIdx.x;
    int d = threadIdx.x;
    __shared__ float hsh[DD];
    float hv = g_h[i * DD + d];
    hsh[d] = hv;
    __syncthreads();

    out[NN + NN * 5 + NN * 5 + i * DD + d] = hv;   // h copy

    if (d < 5) {
        float s = bi[d];
        #pragma unroll 8
        for (int k = 0; k < DD; ++k) s = fmaf(hsh[k], Wi[k * 5 + d], s);
        out[NN + i * 5 + d] = s;
        float s2 = ba[d];
        #pragma unroll 8
        for (int k = 0; k < DD; ++k) s2 = fmaf(hsh[k], Wa[k * 5 + d], s2);
        out[NN + NN * 5 + i * 5 + d] = s2;
    }
    if (d == 5) {
        float s = bt[0];
        #pragma unroll 8
        for (int k = 0; k < DD; ++k) s = fmaf(hsh[k], Wt[k], s);
        out[i] = 5.0f / (1.0f + expf(-s));
    }
}

// ---------------- launcher ---------------------------------------------------
extern "C" void kernel_launch(void* const* d_in, const int* in_sizes, int n_in,
                              void* d_out, int out_size) {
    const float* nf    = (const float*)d_in[0];
    const float* adj   = (const float*)d_in[1];
    const float* Wp    = (const float*)d_in[2];
    const float* bp    = (const float*)d_in[3];
    const float* Wm    = (const float*)d_in[4];
    const float* bm    = (const float*)d_in[5];
    const float* Wu    = (const float*)d_in[6];
    const float* bu    = (const float*)d_in[7];
    const float* gamma = (const float*)d_in[8];
    const float* beta  = (const float*)d_in[9];
    const float* Wt    = (const float*)d_in[10];
    const float* bt    = (const float*)d_in[11];
    const float* Wi    = (const float*)d_in[12];
    const float* bi    = (const float*)d_in[13];
    const float* Wa    = (const float*)d_in[14];
    const float* ba    = (const float*)d_in[15];
    float* out = (float*)d_out;

    dim3 gblk(DD, ACR);
    k_proj_ac<<<NN / ACR, gblk>>>(nf, Wp, bp, Wm, bm);
    for (int l = 0; l < NL; ++l) {
        dim3 ablk(64, YD);
        k_agg<<<(NN + IPB - 1) / IPB, ablk>>>(adj);
        k_upac<<<NN / ACR, gblk>>>(Wu, bu, gamma, beta, Wm, bm, l, (l + 1 < NL) ? 1 : 0);
    }
    k_heads<<<NN, DD>>>(Wt, bt, Wi, bi, Wa, ba, out);
}